// round 5
// baseline (speedup 1.0000x reference)
#include <cuda_runtime.h>
#include <cstdint>

// C[2048,4096] = A[2048,4096] @ W[4096,4096]^T + bias
// W dequantized from 4-bit codebook codes.
// GEMM via warp-level mma.sync tf32 (tcgen05 is feature-gated off by the
// harness's compute_103 PTX target).
// R5: 512 threads / 16 warps (4 per SMSP), 64x32 warp tiles, acc=64 regs,
// A pre-rounded to tf32 (no cvt in mainloop), 3-stage cp.async pipeline.

constexpr int KDIM = 4096;
constexpr int NDIM = 4096;
constexpr int MDIM = 2048;

__device__ float g_W[(size_t)NDIM * KDIM];   // dequantized, tf32-rounded
__device__ float g_A[(size_t)MDIM * KDIM];   // activations, tf32-rounded

__device__ __forceinline__ float to_tf32(float v) {
    uint32_t b;
    asm("cvt.rna.tf32.f32 %0, %1;" : "=r"(b) : "f"(v));
    return __uint_as_float(b);
}

// ---------------------------------------------------------------------------
// Phase 1a: dequantize W (one row per block), store tf32-rounded.
// ---------------------------------------------------------------------------
__global__ void dequant_kernel(const float* __restrict__ codebooks,
                               const int* __restrict__ codes) {
    const int r = blockIdx.x;
    __shared__ float cb[512];
    const float* cbr = codebooks + (size_t)r * 512;
    for (int i = threadIdx.x; i < 512; i += 256) cb[i] = cbr[i];
    __syncthreads();

    const int4* codes_r = (const int4*)(codes + (size_t)r * KDIM);
    float4* w_r = (float4*)(g_W + (size_t)r * KDIM);
    #pragma unroll
    for (int it = 0; it < 4; it++) {
        int i = threadIdx.x + it * 256;
        int4 c = codes_r[i];
        const float* cbg = cb + ((i >> 5) << 4);
        w_r[i] = make_float4(to_tf32(cbg[c.x]), to_tf32(cbg[c.y]),
                             to_tf32(cbg[c.z]), to_tf32(cbg[c.w]));
    }
}

// ---------------------------------------------------------------------------
// Phase 1b: round A to tf32 (keeps cvt out of the GEMM mainloop).
// ---------------------------------------------------------------------------
__global__ void aconv_kernel(const float* __restrict__ x) {
    size_t i = ((size_t)blockIdx.x * 256 + threadIdx.x);
    const float4 v = ((const float4*)x)[i];
    ((float4*)g_A)[i] = make_float4(to_tf32(v.x), to_tf32(v.y),
                                    to_tf32(v.z), to_tf32(v.w));
}

// ---------------------------------------------------------------------------
// Phase 2: tf32 mma.sync GEMM. Block 128x256x32, 16 warps, warp tile 64x32.
// ---------------------------------------------------------------------------
constexpr int BM = 128, BN = 256, BK = 32;
constexpr int NTHREADS = 512;
constexpr int STRIDE = BK + 4;                       // 36 floats
constexpr int A_STAGE = BM * STRIDE;                 // 4608 floats
constexpr int B_STAGE = BN * STRIDE;                 // 9216 floats
constexpr int STAGE   = A_STAGE + B_STAGE;           // 13824 floats
constexpr int NSTAGE  = 3;
constexpr int SMEM_DYN = STAGE * NSTAGE * 4;         // 165888 bytes
constexpr int KITERS = KDIM / BK;                    // 128

extern __shared__ float smf[];

__device__ __forceinline__ void cp_async16(uint32_t dst, const void* src) {
    asm volatile("cp.async.cg.shared.global [%0], [%1], 16;"
                 :: "r"(dst), "l"(src));
}

__device__ __forceinline__ uint32_t smem_u32(const void* p) {
    uint32_t a;
    asm("{ .reg .u64 t; cvta.to.shared.u64 t, %1; cvt.u32.u64 %0, t; }"
        : "=r"(a) : "l"(p));
    return a;
}

__device__ __forceinline__ void mma_tf32(float* c, const uint32_t* a,
                                         const uint32_t* b) {
    asm volatile(
        "mma.sync.aligned.m16n8k8.row.col.f32.tf32.tf32.f32 "
        "{%0,%1,%2,%3}, {%4,%5,%6,%7}, {%8,%9}, {%0,%1,%2,%3};"
        : "+f"(c[0]), "+f"(c[1]), "+f"(c[2]), "+f"(c[3])
        : "r"(a[0]), "r"(a[1]), "r"(a[2]), "r"(a[3]), "r"(b[0]), "r"(b[1]));
}

__device__ __forceinline__ void load_tile(uint32_t sbase,
                                          const float* __restrict__ Ab,
                                          const float* __restrict__ Bb,
                                          int k0, int tid) {
    // A: 128 rows x 8 float4 = 1024 chunks; 2 per thread
    #pragma unroll
    for (int j = 0; j < 2; j++) {
        int i = tid + j * NTHREADS;
        int row = i >> 3, ci = (i & 7) * 4;
        cp_async16(sbase + (uint32_t)(row * STRIDE + ci) * 4,
                   Ab + (size_t)row * KDIM + k0 + ci);
    }
    // B: 256 rows x 8 float4 = 2048 chunks; 4 per thread
    const uint32_t sb = sbase + A_STAGE * 4;
    #pragma unroll
    for (int j = 0; j < 4; j++) {
        int i = tid + j * NTHREADS;
        int row = i >> 3, ci = (i & 7) * 4;
        cp_async16(sb + (uint32_t)(row * STRIDE + ci) * 4,
                   Bb + (size_t)row * KDIM + k0 + ci);
    }
    asm volatile("cp.async.commit_group;" ::: "memory");
}

__global__ void __launch_bounds__(NTHREADS, 1)
gemm_mma_kernel(const float* __restrict__ bias, float* __restrict__ C) {
    const int tid  = threadIdx.x;
    const int wid  = tid >> 5;
    const int lane = tid & 31;
    const int gid  = lane >> 2;      // group of 4
    const int tig  = lane & 3;       // thread in group

    const int m0 = blockIdx.y * BM;
    const int n0 = blockIdx.x * BN;
    const int wm = (wid >> 3) * 64;  // warp grid 2(M) x 8(N), tile 64x32
    const int wn = (wid & 7) * 32;

    const uint32_t smem_base = smem_u32(smf);
    const float* Ab = g_A + (size_t)m0 * KDIM;
    const float* Bb = g_W + (size_t)n0 * KDIM;

    float acc[4][4][4] = {};   // mt(4 x 16 rows) x nt(4 x 8 cols)

    // prologue: stages 0 and 1 in flight
    load_tile(smem_base,             Ab, Bb, 0,  tid);
    load_tile(smem_base + STAGE * 4, Ab, Bb, BK, tid);

    for (int it = 0; it < KITERS; it++) {
        if (it + 1 < KITERS) {
            asm volatile("cp.async.wait_group 1;" ::: "memory");
        } else {
            asm volatile("cp.async.wait_group 0;" ::: "memory");
        }
        __syncthreads();

        if (it + 2 < KITERS) {
            load_tile(smem_base + (uint32_t)((it + 2) % NSTAGE) * STAGE * 4,
                      Ab, Bb, (it + 2) * BK, tid);
        }

        const float* sA = smf + (it % NSTAGE) * STAGE;
        const float* sB = sA + A_STAGE;

        #pragma unroll
        for (int ks = 0; ks < 4; ks++) {
            const int kb = ks * 8;
            uint32_t af[4][4], bf[4][2];
            #pragma unroll
            for (int mt = 0; mt < 4; mt++) {
                const float* p = sA + (wm + mt * 16 + gid) * STRIDE + kb + tig;
                af[mt][0] = __float_as_uint(p[0]);
                af[mt][1] = __float_as_uint(p[8 * STRIDE]);
                af[mt][2] = __float_as_uint(p[4]);
                af[mt][3] = __float_as_uint(p[8 * STRIDE + 4]);
            }
            #pragma unroll
            for (int nt = 0; nt < 4; nt++) {
                const float* p = sB + (wn + nt * 8 + gid) * STRIDE + kb + tig;
                bf[nt][0] = __float_as_uint(p[0]);
                bf[nt][1] = __float_as_uint(p[4]);
            }
            #pragma unroll
            for (int mt = 0; mt < 4; mt++)
                #pragma unroll
                for (int nt = 0; nt < 4; nt++)
                    mma_tf32(acc[mt][nt], af[mt], bf[nt]);
        }
    }

    // epilogue: bias + store
    #pragma unroll
    for (int mt = 0; mt < 4; mt++) {
        #pragma unroll
        for (int nt = 0; nt < 4; nt++) {
            const int r0 = m0 + wm + mt * 16 + gid;
            const int c  = n0 + wn + nt * 8 + tig * 2;
            const float2 b2 = *(const float2*)(bias + c);
            float2 o0, o1;
            o0.x = acc[mt][nt][0] + b2.x;
            o0.y = acc[mt][nt][1] + b2.y;
            o1.x = acc[mt][nt][2] + b2.x;
            o1.y = acc[mt][nt][3] + b2.y;
            *(float2*)(C + (size_t)r0 * NDIM + c)       = o0;
            *(float2*)(C + (size_t)(r0 + 8) * NDIM + c) = o1;
        }
    }
}

// ---------------------------------------------------------------------------
extern "C" void kernel_launch(void* const* d_in, const int* in_sizes, int n_in,
                              void* d_out, int out_size) {
    const float* x         = (const float*)d_in[0];
    const float* codebooks = (const float*)d_in[1];
    const int*   codes     = (const int*)d_in[2];
    const float* bias      = (const float*)d_in[3];
    float* out = (float*)d_out;

    dequant_kernel<<<NDIM, 256>>>(codebooks, codes);
    aconv_kernel<<<(MDIM * KDIM / 4) / 256, 256>>>(x);

    cudaFuncSetAttribute(gemm_mma_kernel,
                         cudaFuncAttributeMaxDynamicSharedMemorySize, SMEM_DYN);
    dim3 grid(NDIM / BN, MDIM / BM);   // (16, 16)
    gemm_mma_kernel<<<grid, NTHREADS, SMEM_DYN>>>(bias, out);
}

// round 6
// speedup vs baseline: 1.6923x; 1.6923x over previous
#include <cuda_runtime.h>
#include <cuda_fp16.h>
#include <cstdint>

// C[2048,4096] = A[2048,4096] @ W[4096,4096]^T + bias
// W dequantized from 4-bit codebook codes.
// R6: fp16 mma.sync m16n8k16 (2x FLOP/instr vs tf32, same 10-bit mantissa).
// W and A stored as __half: halves LDS, smem, L2 traffic, dequant writes.

constexpr int KDIM = 4096;
constexpr int NDIM = 4096;
constexpr int MDIM = 2048;

__device__ __half g_W[(size_t)NDIM * KDIM];   // dequantized fp16
__device__ __half g_A[(size_t)MDIM * KDIM];   // activations fp16

// ---------------------------------------------------------------------------
// Phase 1a: dequantize W -> fp16 (one row per block).
// ---------------------------------------------------------------------------
__global__ void dequant_kernel(const float* __restrict__ codebooks,
                               const int* __restrict__ codes) {
    const int r = blockIdx.x;
    __shared__ float cb[512];
    const float* cbr = codebooks + (size_t)r * 512;
    for (int i = threadIdx.x; i < 512; i += 256) cb[i] = cbr[i];
    __syncthreads();

    const int4* codes_r = (const int4*)(codes + (size_t)r * KDIM);
    __half2* w2 = (__half2*)(g_W + (size_t)r * KDIM);
    #pragma unroll
    for (int it = 0; it < 4; it++) {
        int i = threadIdx.x + it * 256;
        int4 c = codes_r[i];
        const float* cbg = cb + ((i >> 5) << 4);
        w2[2 * i]     = __floats2half2_rn(cbg[c.x], cbg[c.y]);
        w2[2 * i + 1] = __floats2half2_rn(cbg[c.z], cbg[c.w]);
    }
}

// ---------------------------------------------------------------------------
// Phase 1b: convert A -> fp16.
// ---------------------------------------------------------------------------
__global__ void aconv_kernel(const float* __restrict__ x) {
    size_t i = ((size_t)blockIdx.x * 256 + threadIdx.x);
    const float4 v = ((const float4*)x)[i];
    __half2* a2 = (__half2*)g_A;
    a2[2 * i]     = __floats2half2_rn(v.x, v.y);
    a2[2 * i + 1] = __floats2half2_rn(v.z, v.w);
}

// ---------------------------------------------------------------------------
// Phase 2: fp16 mma.sync GEMM. Block 128x256x32(halfs), 8 warps,
// warp tile 64x64, 3-stage cp.async, one barrier per K-iter.
// ---------------------------------------------------------------------------
constexpr int BM = 128, BN = 256, BK = 32;
constexpr int STRIDE = 40;                            // halfs; bank-bijective
constexpr int A_STAGE = BM * STRIDE;                  // 5120 halfs
constexpr int B_STAGE = BN * STRIDE;                  // 10240 halfs
constexpr int STAGE   = A_STAGE + B_STAGE;            // 15360 halfs (30720 B)
constexpr int NSTAGE  = 3;
constexpr int SMEM_DYN = STAGE * NSTAGE * 2;          // 92160 bytes
constexpr int KITERS = KDIM / BK;                     // 128

extern __shared__ __half smh[];

__device__ __forceinline__ uint32_t smem_u32(const void* p) {
    uint32_t a;
    asm("{ .reg .u64 t; cvta.to.shared.u64 t, %1; cvt.u32.u64 %0, t; }"
        : "=r"(a) : "l"(p));
    return a;
}

__device__ __forceinline__ void cp_async16(uint32_t dst, const void* src) {
    asm volatile("cp.async.cg.shared.global [%0], [%1], 16;"
                 :: "r"(dst), "l"(src));
}

__device__ __forceinline__ void mma_f16(float* c, const uint32_t* a,
                                        const uint32_t* b) {
    asm volatile(
        "mma.sync.aligned.m16n8k16.row.col.f32.f16.f16.f32 "
        "{%0,%1,%2,%3}, {%4,%5,%6,%7}, {%8,%9}, {%0,%1,%2,%3};"
        : "+f"(c[0]), "+f"(c[1]), "+f"(c[2]), "+f"(c[3])
        : "r"(a[0]), "r"(a[1]), "r"(a[2]), "r"(a[3]), "r"(b[0]), "r"(b[1]));
}

__device__ __forceinline__ void load_tile(uint32_t sbase,
                                          const __half* __restrict__ Ab,
                                          const __half* __restrict__ Bb,
                                          int k0, int tid) {
    // A: 128 rows x 4 chunks(8 halfs) = 512; 2 per thread
    #pragma unroll
    for (int j = 0; j < 2; j++) {
        int i = tid + j * 256;
        int row = i >> 2, c = (i & 3) * 8;
        cp_async16(sbase + (uint32_t)(row * STRIDE + c) * 2,
                   Ab + (size_t)row * KDIM + k0 + c);
    }
    // B: 256 rows x 4 chunks = 1024; 4 per thread
    const uint32_t sb = sbase + A_STAGE * 2;
    #pragma unroll
    for (int j = 0; j < 4; j++) {
        int i = tid + j * 256;
        int row = i >> 2, c = (i & 3) * 8;
        cp_async16(sb + (uint32_t)(row * STRIDE + c) * 2,
                   Bb + (size_t)row * KDIM + k0 + c);
    }
    asm volatile("cp.async.commit_group;" ::: "memory");
}

__global__ void __launch_bounds__(256, 1)
gemm_mma_kernel(const float* __restrict__ bias, float* __restrict__ C) {
    const int tid  = threadIdx.x;
    const int wid  = tid >> 5;
    const int lane = tid & 31;
    const int gid  = lane >> 2;      // group of 4
    const int tig  = lane & 3;       // thread in group

    const int m0 = blockIdx.y * BM;
    const int n0 = blockIdx.x * BN;
    const int wm = (wid >> 2) * 64;  // warp grid 2(M) x 4(N), tile 64x64
    const int wn = (wid & 3) * 64;

    const uint32_t smem_base = smem_u32(smh);
    const __half* Ab = g_A + (size_t)m0 * KDIM;
    const __half* Bb = g_W + (size_t)n0 * KDIM;

    float acc[4][8][4] = {};

    load_tile(smem_base,                 Ab, Bb, 0,  tid);
    load_tile(smem_base + STAGE * 2,     Ab, Bb, BK, tid);

    for (int it = 0; it < KITERS; it++) {
        if (it + 1 < KITERS) {
            asm volatile("cp.async.wait_group 1;" ::: "memory");
        } else {
            asm volatile("cp.async.wait_group 0;" ::: "memory");
        }
        __syncthreads();

        if (it + 2 < KITERS) {
            load_tile(smem_base + (uint32_t)((it + 2) % NSTAGE) * STAGE * 2,
                      Ab, Bb, (it + 2) * BK, tid);
        }

        const __half* sA = smh + (it % NSTAGE) * STAGE;
        const __half* sB = sA + A_STAGE;

        #pragma unroll
        for (int ks = 0; ks < 2; ks++) {            // 2 x K=16 steps
            const int kb = ks * 16;
            uint32_t af[4][4], bf[8][2];
            #pragma unroll
            for (int mt = 0; mt < 4; mt++) {
                // a0: row gid,   k = kb + 2*tig .. +1   (packed half2)
                // a1: row gid+8; a2: k += 8; a3: both
                const __half* p = sA + (wm + mt * 16 + gid) * STRIDE + kb + 2 * tig;
                af[mt][0] = *(const uint32_t*)(p);
                af[mt][1] = *(const uint32_t*)(p + 8 * STRIDE);
                af[mt][2] = *(const uint32_t*)(p + 8);
                af[mt][3] = *(const uint32_t*)(p + 8 * STRIDE + 8);
            }
            #pragma unroll
            for (int nt = 0; nt < 8; nt++) {
                // b0: n = gid, k = kb + 2*tig .. +1 ; b1: k += 8
                const __half* p = sB + (wn + nt * 8 + gid) * STRIDE + kb + 2 * tig;
                bf[nt][0] = *(const uint32_t*)(p);
                bf[nt][1] = *(const uint32_t*)(p + 8);
            }
            #pragma unroll
            for (int mt = 0; mt < 4; mt++)
                #pragma unroll
                for (int nt = 0; nt < 8; nt++)
                    mma_f16(acc[mt][nt], af[mt], bf[nt]);
        }
    }

    // epilogue: bias + store
    #pragma unroll
    for (int mt = 0; mt < 4; mt++) {
        #pragma unroll
        for (int nt = 0; nt < 8; nt++) {
            const int r0 = m0 + wm + mt * 16 + gid;
            const int c  = n0 + wn + nt * 8 + tig * 2;
            const float2 b2 = *(const float2*)(bias + c);
            float2 o0, o1;
            o0.x = acc[mt][nt][0] + b2.x;
            o0.y = acc[mt][nt][1] + b2.y;
            o1.x = acc[mt][nt][2] + b2.x;
            o1.y = acc[mt][nt][3] + b2.y;
            *(float2*)(C + (size_t)r0 * NDIM + c)       = o0;
            *(float2*)(C + (size_t)(r0 + 8) * NDIM + c) = o1;
        }
    }
}

// ---------------------------------------------------------------------------
extern "C" void kernel_launch(void* const* d_in, const int* in_sizes, int n_in,
                              void* d_out, int out_size) {
    const float* x         = (const float*)d_in[0];
    const float* codebooks = (const float*)d_in[1];
    const int*   codes     = (const int*)d_in[2];
    const float* bias      = (const float*)d_in[3];
    float* out = (float*)d_out;

    dequant_kernel<<<NDIM, 256>>>(codebooks, codes);
    aconv_kernel<<<(MDIM * KDIM / 4) / 256, 256>>>(x);

    cudaFuncSetAttribute(gemm_mma_kernel,
                         cudaFuncAttributeMaxDynamicSharedMemorySize, SMEM_DYN);
    dim3 grid(NDIM / BN, MDIM / BM);   // (16, 16)
    gemm_mma_kernel<<<grid, 256, SMEM_DYN>>>(bias, out);
}

// round 7
// speedup vs baseline: 1.7386x; 1.0273x over previous
#include <cuda_runtime.h>
#include <cuda_fp16.h>
#include <cstdint>

// C[2048,4096] = A[2048,4096] @ W[4096,4096]^T + bias
// W dequantized from 4-bit codebook codes.
// R7: fp16 mma.sync m16n8k16 + ldmatrix.x4 fragment loads
// (16 ldmatrix vs 64 LDS.32 per warp-iter).

constexpr int KDIM = 4096;
constexpr int NDIM = 4096;
constexpr int MDIM = 2048;

__device__ __half g_W[(size_t)NDIM * KDIM];   // dequantized fp16
__device__ __half g_A[(size_t)MDIM * KDIM];   // activations fp16

// ---------------------------------------------------------------------------
// Phase 1a: dequantize W -> fp16 (one row per block).
// ---------------------------------------------------------------------------
__global__ void dequant_kernel(const float* __restrict__ codebooks,
                               const int* __restrict__ codes) {
    const int r = blockIdx.x;
    __shared__ float cb[512];
    const float* cbr = codebooks + (size_t)r * 512;
    for (int i = threadIdx.x; i < 512; i += 256) cb[i] = cbr[i];
    __syncthreads();

    const int4* codes_r = (const int4*)(codes + (size_t)r * KDIM);
    __half2* w2 = (__half2*)(g_W + (size_t)r * KDIM);
    #pragma unroll
    for (int it = 0; it < 4; it++) {
        int i = threadIdx.x + it * 256;
        int4 c = codes_r[i];
        const float* cbg = cb + ((i >> 5) << 4);
        w2[2 * i]     = __floats2half2_rn(cbg[c.x], cbg[c.y]);
        w2[2 * i + 1] = __floats2half2_rn(cbg[c.z], cbg[c.w]);
    }
}

// ---------------------------------------------------------------------------
// Phase 1b: convert A -> fp16.
// ---------------------------------------------------------------------------
__global__ void aconv_kernel(const float* __restrict__ x) {
    size_t i = ((size_t)blockIdx.x * 256 + threadIdx.x);
    const float4 v = ((const float4*)x)[i];
    __half2* a2 = (__half2*)g_A;
    a2[2 * i]     = __floats2half2_rn(v.x, v.y);
    a2[2 * i + 1] = __floats2half2_rn(v.z, v.w);
}

// ---------------------------------------------------------------------------
// Phase 2: fp16 mma.sync GEMM. Block 128x256x32(halfs), 8 warps,
// warp tile 64x64, 3-stage cp.async, ldmatrix fragment loads.
// ---------------------------------------------------------------------------
constexpr int BM = 128, BN = 256, BK = 32;
constexpr int STRIDE = 40;                            // halfs; bank-bijective
constexpr int A_STAGE = BM * STRIDE;                  // 5120 halfs
constexpr int B_STAGE = BN * STRIDE;                  // 10240 halfs
constexpr int STAGE   = A_STAGE + B_STAGE;            // 15360 halfs (30720 B)
constexpr int NSTAGE  = 3;
constexpr int SMEM_DYN = STAGE * NSTAGE * 2;          // 92160 bytes
constexpr int KITERS = KDIM / BK;                     // 128

extern __shared__ __half smh[];

__device__ __forceinline__ uint32_t smem_u32(const void* p) {
    uint32_t a;
    asm("{ .reg .u64 t; cvta.to.shared.u64 t, %1; cvt.u32.u64 %0, t; }"
        : "=r"(a) : "l"(p));
    return a;
}

__device__ __forceinline__ void cp_async16(uint32_t dst, const void* src) {
    asm volatile("cp.async.cg.shared.global [%0], [%1], 16;"
                 :: "r"(dst), "l"(src));
}

__device__ __forceinline__ void ldmatrix_x4(uint32_t* r, uint32_t addr) {
    asm volatile(
        "ldmatrix.sync.aligned.m8n8.x4.shared.b16 {%0, %1, %2, %3}, [%4];"
        : "=r"(r[0]), "=r"(r[1]), "=r"(r[2]), "=r"(r[3])
        : "r"(addr));
}

__device__ __forceinline__ void mma_f16(float* c, const uint32_t* a,
                                        const uint32_t* b) {
    asm volatile(
        "mma.sync.aligned.m16n8k16.row.col.f32.f16.f16.f32 "
        "{%0,%1,%2,%3}, {%4,%5,%6,%7}, {%8,%9}, {%0,%1,%2,%3};"
        : "+f"(c[0]), "+f"(c[1]), "+f"(c[2]), "+f"(c[3])
        : "r"(a[0]), "r"(a[1]), "r"(a[2]), "r"(a[3]), "r"(b[0]), "r"(b[1]));
}

__device__ __forceinline__ void load_tile(uint32_t sbase,
                                          const __half* __restrict__ Ab,
                                          const __half* __restrict__ Bb,
                                          int k0, int tid) {
    // A: 128 rows x 4 chunks(8 halfs) = 512; 2 per thread
    #pragma unroll
    for (int j = 0; j < 2; j++) {
        int i = tid + j * 256;
        int row = i >> 2, c = (i & 3) * 8;
        cp_async16(sbase + (uint32_t)(row * STRIDE + c) * 2,
                   Ab + (size_t)row * KDIM + k0 + c);
    }
    // B: 256 rows x 4 chunks = 1024; 4 per thread
    const uint32_t sb = sbase + A_STAGE * 2;
    #pragma unroll
    for (int j = 0; j < 4; j++) {
        int i = tid + j * 256;
        int row = i >> 2, c = (i & 3) * 8;
        cp_async16(sb + (uint32_t)(row * STRIDE + c) * 2,
                   Bb + (size_t)row * KDIM + k0 + c);
    }
    asm volatile("cp.async.commit_group;" ::: "memory");
}

__global__ void __launch_bounds__(256, 1)
gemm_mma_kernel(const float* __restrict__ bias, float* __restrict__ C) {
    const int tid  = threadIdx.x;
    const int wid  = tid >> 5;
    const int lane = tid & 31;
    const int gid  = lane >> 2;      // group of 4
    const int tig  = lane & 3;       // thread in group

    const int m0 = blockIdx.y * BM;
    const int n0 = blockIdx.x * BN;
    const int wm = (wid >> 2) * 64;  // warp grid 2(M) x 4(N), tile 64x64
    const int wn = (wid & 3) * 64;

    const uint32_t smem_base = smem_u32(smh);
    const __half* Ab = g_A + (size_t)m0 * KDIM;
    const __half* Bb = g_W + (size_t)n0 * KDIM;

    // ldmatrix per-lane address offsets (in halfs, converted to bytes below)
    // A x4 @ (mt, kb): matrices [rows 0-7 | rows 8-15 | rows 0-7,k+8 | rows 8-15,k+8]
    //   lane l -> row (l&15), col ((l>>4)<<3)
    const uint32_t a_lane = (uint32_t)((lane & 15) * STRIDE + ((lane >> 4) << 3)) * 2;
    // B x4 @ (p, kb): [n 0-7,k | n 0-7,k+8 | n 8-15,k | n 8-15,k+8]
    //   lane l -> n-row ((l>>4)<<3) + (l&7), col (l&8)
    const uint32_t b_lane = (uint32_t)((((lane >> 4) << 3) + (lane & 7)) * STRIDE
                                       + (lane & 8)) * 2;

    float acc[4][8][4] = {};

    load_tile(smem_base,             Ab, Bb, 0,  tid);
    load_tile(smem_base + STAGE * 2, Ab, Bb, BK, tid);

    for (int it = 0; it < KITERS; it++) {
        if (it + 1 < KITERS) {
            asm volatile("cp.async.wait_group 1;" ::: "memory");
        } else {
            asm volatile("cp.async.wait_group 0;" ::: "memory");
        }
        __syncthreads();

        if (it + 2 < KITERS) {
            load_tile(smem_base + (uint32_t)((it + 2) % NSTAGE) * STAGE * 2,
                      Ab, Bb, (it + 2) * BK, tid);
        }

        const uint32_t sA = smem_base + (uint32_t)(it % NSTAGE) * STAGE * 2;
        const uint32_t sB = sA + A_STAGE * 2;

        #pragma unroll
        for (int ks = 0; ks < 2; ks++) {            // 2 x K=16 steps
            const int kb = ks * 16;
            uint32_t af[4][4], bf[4][4];            // bf[p] covers nt=2p,2p+1
            #pragma unroll
            for (int mt = 0; mt < 4; mt++) {
                ldmatrix_x4(af[mt],
                            sA + (uint32_t)((wm + mt * 16) * STRIDE + kb) * 2
                               + a_lane);
            }
            #pragma unroll
            for (int p = 0; p < 4; p++) {
                ldmatrix_x4(bf[p],
                            sB + (uint32_t)((wn + p * 16) * STRIDE + kb) * 2
                               + b_lane);
            }
            #pragma unroll
            for (int mt = 0; mt < 4; mt++) {
                #pragma unroll
                for (int p = 0; p < 4; p++) {
                    mma_f16(acc[mt][2 * p],     af[mt], &bf[p][0]);
                    mma_f16(acc[mt][2 * p + 1], af[mt], &bf[p][2]);
                }
            }
        }
    }

    // epilogue: bias + store
    #pragma unroll
    for (int mt = 0; mt < 4; mt++) {
        #pragma unroll
        for (int nt = 0; nt < 8; nt++) {
            const int r0 = m0 + wm + mt * 16 + gid;
            const int c  = n0 + wn + nt * 8 + tig * 2;
            const float2 b2 = *(const float2*)(bias + c);
            float2 o0, o1;
            o0.x = acc[mt][nt][0] + b2.x;
            o0.y = acc[mt][nt][1] + b2.y;
            o1.x = acc[mt][nt][2] + b2.x;
            o1.y = acc[mt][nt][3] + b2.y;
            *(float2*)(C + (size_t)r0 * NDIM + c)       = o0;
            *(float2*)(C + (size_t)(r0 + 8) * NDIM + c) = o1;
        }
    }
}

// ---------------------------------------------------------------------------
extern "C" void kernel_launch(void* const* d_in, const int* in_sizes, int n_in,
                              void* d_out, int out_size) {
    const float* x         = (const float*)d_in[0];
    const float* codebooks = (const float*)d_in[1];
    const int*   codes     = (const int*)d_in[2];
    const float* bias      = (const float*)d_in[3];
    float* out = (float*)d_out;

    dequant_kernel<<<NDIM, 256>>>(codebooks, codes);
    aconv_kernel<<<(MDIM * KDIM / 4) / 256, 256>>>(x);

    cudaFuncSetAttribute(gemm_mma_kernel,
                         cudaFuncAttributeMaxDynamicSharedMemorySize, SMEM_DYN);
    dim3 grid(NDIM / BN, MDIM / BM);   // (16, 16)
    gemm_mma_kernel<<<grid, 256, SMEM_DYN>>>(bias, out);
}

// round 8
// speedup vs baseline: 2.3067x; 1.3267x over previous
#include <cuda_runtime.h>
#include <cuda_fp16.h>
#include <cstdint>

// C[2048,4096] = A[2048,4096] @ W[4096,4096]^T + bias
// W dequantized from 4-bit codebook codes.
// R8: 2 CTAs/SM (tile 128x128, 4 warps, 64x64 warp tiles) so one CTA's
// barrier/pipeline bubbles are covered by the other CTA's mma stream.
// dequant + A-conversion merged into one prep kernel.

constexpr int KDIM = 4096;
constexpr int NDIM = 4096;
constexpr int MDIM = 2048;

__device__ __half g_W[(size_t)NDIM * KDIM];   // dequantized fp16
__device__ __half g_A[(size_t)MDIM * KDIM];   // activations fp16

// ---------------------------------------------------------------------------
// Phase 1: merged prep. Blocks [0,4096): dequant W row. Blocks [4096,4608):
// convert x -> fp16.
// ---------------------------------------------------------------------------
constexpr int ACONV_BLOCKS = 512;
constexpr int ACHUNKS = MDIM * KDIM / 4;      // float4 chunks = 2097152

__global__ void prep_kernel(const float* __restrict__ codebooks,
                            const int* __restrict__ codes,
                            const float* __restrict__ x) {
    if (blockIdx.x < NDIM) {
        const int r = blockIdx.x;
        __shared__ float cb[512];
        const float* cbr = codebooks + (size_t)r * 512;
        for (int i = threadIdx.x; i < 512; i += 256) cb[i] = cbr[i];
        __syncthreads();

        const int4* codes_r = (const int4*)(codes + (size_t)r * KDIM);
        __half2* w2 = (__half2*)(g_W + (size_t)r * KDIM);
        #pragma unroll
        for (int it = 0; it < 4; it++) {
            int i = threadIdx.x + it * 256;
            int4 c = codes_r[i];
            const float* cbg = cb + ((i >> 5) << 4);
            w2[2 * i]     = __floats2half2_rn(cbg[c.x], cbg[c.y]);
            w2[2 * i + 1] = __floats2half2_rn(cbg[c.z], cbg[c.w]);
        }
    } else {
        const int b = blockIdx.x - NDIM;
        __half2* a2 = (__half2*)g_A;
        #pragma unroll
        for (int it = 0; it < ACHUNKS / (ACONV_BLOCKS * 256); it++) {
            size_t i = (size_t)it * ACONV_BLOCKS * 256 + (size_t)b * 256 + threadIdx.x;
            const float4 v = ((const float4*)x)[i];
            a2[2 * i]     = __floats2half2_rn(v.x, v.y);
            a2[2 * i + 1] = __floats2half2_rn(v.z, v.w);
        }
    }
}

// ---------------------------------------------------------------------------
// Phase 2: fp16 mma.sync GEMM. Block 128x128x32(halfs), 4 warps,
// warp tile 64x64, 3-stage cp.async, ldmatrix, 2 CTAs/SM.
// ---------------------------------------------------------------------------
constexpr int BM = 128, BN = 128, BK = 32;
constexpr int NTHREADS = 128;
constexpr int STRIDE = 40;                            // halfs; bank-bijective
constexpr int A_STAGE = BM * STRIDE;                  // 5120 halfs
constexpr int B_STAGE = BN * STRIDE;                  // 5120 halfs
constexpr int STAGE   = A_STAGE + B_STAGE;            // 10240 halfs (20480 B)
constexpr int NSTAGE  = 3;
constexpr int SMEM_DYN = STAGE * NSTAGE * 2;          // 61440 bytes
constexpr int KITERS = KDIM / BK;                     // 128

extern __shared__ __half smh[];

__device__ __forceinline__ uint32_t smem_u32(const void* p) {
    uint32_t a;
    asm("{ .reg .u64 t; cvta.to.shared.u64 t, %1; cvt.u32.u64 %0, t; }"
        : "=r"(a) : "l"(p));
    return a;
}

__device__ __forceinline__ void cp_async16(uint32_t dst, const void* src) {
    asm volatile("cp.async.cg.shared.global [%0], [%1], 16;"
                 :: "r"(dst), "l"(src));
}

__device__ __forceinline__ void ldmatrix_x4(uint32_t* r, uint32_t addr) {
    asm volatile(
        "ldmatrix.sync.aligned.m8n8.x4.shared.b16 {%0, %1, %2, %3}, [%4];"
        : "=r"(r[0]), "=r"(r[1]), "=r"(r[2]), "=r"(r[3])
        : "r"(addr));
}

__device__ __forceinline__ void mma_f16(float* c, const uint32_t* a,
                                        const uint32_t* b) {
    asm volatile(
        "mma.sync.aligned.m16n8k16.row.col.f32.f16.f16.f32 "
        "{%0,%1,%2,%3}, {%4,%5,%6,%7}, {%8,%9}, {%0,%1,%2,%3};"
        : "+f"(c[0]), "+f"(c[1]), "+f"(c[2]), "+f"(c[3])
        : "r"(a[0]), "r"(a[1]), "r"(a[2]), "r"(a[3]), "r"(b[0]), "r"(b[1]));
}

__device__ __forceinline__ void load_tile(uint32_t sbase,
                                          const __half* __restrict__ Ab,
                                          const __half* __restrict__ Bb,
                                          int k0, int tid) {
    // A: 128 rows x 4 chunks(8 halfs) = 512; 4 per thread
    #pragma unroll
    for (int j = 0; j < 4; j++) {
        int i = tid + j * NTHREADS;
        int row = i >> 2, c = (i & 3) * 8;
        cp_async16(sbase + (uint32_t)(row * STRIDE + c) * 2,
                   Ab + (size_t)row * KDIM + k0 + c);
    }
    // B: 128 rows x 4 chunks = 512; 4 per thread
    const uint32_t sb = sbase + A_STAGE * 2;
    #pragma unroll
    for (int j = 0; j < 4; j++) {
        int i = tid + j * NTHREADS;
        int row = i >> 2, c = (i & 3) * 8;
        cp_async16(sb + (uint32_t)(row * STRIDE + c) * 2,
                   Bb + (size_t)row * KDIM + k0 + c);
    }
    asm volatile("cp.async.commit_group;" ::: "memory");
}

__global__ void __launch_bounds__(NTHREADS, 2)
gemm_mma_kernel(const float* __restrict__ bias, float* __restrict__ C) {
    const int tid  = threadIdx.x;
    const int wid  = tid >> 5;
    const int lane = tid & 31;
    const int gid  = lane >> 2;      // group of 4
    const int tig  = lane & 3;       // thread in group

    const int m0 = blockIdx.y * BM;
    const int n0 = blockIdx.x * BN;
    const int wm = (wid >> 1) * 64;  // warp grid 2(M) x 2(N), tile 64x64
    const int wn = (wid & 1) * 64;

    const uint32_t smem_base = smem_u32(smh);
    const __half* Ab = g_A + (size_t)m0 * KDIM;
    const __half* Bb = g_W + (size_t)n0 * KDIM;

    // ldmatrix per-lane address offsets (bytes)
    const uint32_t a_lane = (uint32_t)((lane & 15) * STRIDE + ((lane >> 4) << 3)) * 2;
    const uint32_t b_lane = (uint32_t)((((lane >> 4) << 3) + (lane & 7)) * STRIDE
                                       + (lane & 8)) * 2;

    float acc[4][8][4] = {};

    load_tile(smem_base,             Ab, Bb, 0,  tid);
    load_tile(smem_base + STAGE * 2, Ab, Bb, BK, tid);

    for (int it = 0; it < KITERS; it++) {
        if (it + 1 < KITERS) {
            asm volatile("cp.async.wait_group 1;" ::: "memory");
        } else {
            asm volatile("cp.async.wait_group 0;" ::: "memory");
        }
        __syncthreads();

        if (it + 2 < KITERS) {
            load_tile(smem_base + (uint32_t)((it + 2) % NSTAGE) * STAGE * 2,
                      Ab, Bb, (it + 2) * BK, tid);
        }

        const uint32_t sA = smem_base + (uint32_t)(it % NSTAGE) * STAGE * 2;
        const uint32_t sB = sA + A_STAGE * 2;

        #pragma unroll
        for (int ks = 0; ks < 2; ks++) {            // 2 x K=16 steps
            const int kb = ks * 16;
            uint32_t af[4][4], bf[4][4];            // bf[p] covers nt=2p,2p+1
            #pragma unroll
            for (int mt = 0; mt < 4; mt++) {
                ldmatrix_x4(af[mt],
                            sA + (uint32_t)((wm + mt * 16) * STRIDE + kb) * 2
                               + a_lane);
            }
            #pragma unroll
            for (int p = 0; p < 4; p++) {
                ldmatrix_x4(bf[p],
                            sB + (uint32_t)((wn + p * 16) * STRIDE + kb) * 2
                               + b_lane);
            }
            #pragma unroll
            for (int mt = 0; mt < 4; mt++) {
                #pragma unroll
                for (int p = 0; p < 4; p++) {
                    mma_f16(acc[mt][2 * p],     af[mt], &bf[p][0]);
                    mma_f16(acc[mt][2 * p + 1], af[mt], &bf[p][2]);
                }
            }
        }
    }

    // epilogue: bias + store
    #pragma unroll
    for (int mt = 0; mt < 4; mt++) {
        #pragma unroll
        for (int nt = 0; nt < 8; nt++) {
            const int r0 = m0 + wm + mt * 16 + gid;
            const int c  = n0 + wn + nt * 8 + tig * 2;
            const float2 b2 = *(const float2*)(bias + c);
            float2 o0, o1;
            o0.x = acc[mt][nt][0] + b2.x;
            o0.y = acc[mt][nt][1] + b2.y;
            o1.x = acc[mt][nt][2] + b2.x;
            o1.y = acc[mt][nt][3] + b2.y;
            *(float2*)(C + (size_t)r0 * NDIM + c)       = o0;
            *(float2*)(C + (size_t)(r0 + 8) * NDIM + c) = o1;
        }
    }
}

// ---------------------------------------------------------------------------
extern "C" void kernel_launch(void* const* d_in, const int* in_sizes, int n_in,
                              void* d_out, int out_size) {
    const float* x         = (const float*)d_in[0];
    const float* codebooks = (const float*)d_in[1];
    const int*   codes     = (const int*)d_in[2];
    const float* bias      = (const float*)d_in[3];
    float* out = (float*)d_out;

    prep_kernel<<<NDIM + ACONV_BLOCKS, 256>>>(codebooks, codes, x);

    cudaFuncSetAttribute(gemm_mma_kernel,
                         cudaFuncAttributeMaxDynamicSharedMemorySize, SMEM_DYN);
    dim3 grid(NDIM / BN, MDIM / BM);   // (32, 16) = 512 blocks
    gemm_mma_kernel<<<grid, NTHREADS, SMEM_DYN>>>(bias, out);
}